// round 16
// baseline (speedup 1.0000x reference)
#include <cuda_runtime.h>
#include <cuda_fp16.h>
#include <math.h>
#include <stdint.h>

#define B_    256
#define G_    16
#define GS_   588
#define GSP   640
#define HID_  1024
#define FEAT_ 2048
#define NSPL  32
#define KSPL  ((G_ * FEAT_) / NSPL)   // 1024
#define NSPL4 8
#define KSPL4 (HID_ / NSPL4)          // 128

#define THREADS 512
#define BM 128
#define BN 128
#define BK 64
#define BKP 72     // padded A row (halves): 144B stride, conflict-free LDSM
#define BNP 136    // padded B row (halves): 272B stride, conflict-free LDSM

// per-buffer SMEM layout (bytes)
#define PB_AHI 0
#define PB_ALO 18432
#define PB_BHI 36864
#define PB_BLO 54272
#define BUF_BYTES 71680
#define SMEM_TOTAL (2 * BUF_BYTES)   // 143360

// ---------------- scratch (device globals) ----------------
__device__ __half g_qk_hi[(size_t)2 * G_ * B_ * GSP];
__device__ __half g_qk_lo[(size_t)2 * G_ * B_ * GSP];
__device__ __half g_h_hi[(size_t)2 * B_ * G_ * HID_];
__device__ __half g_h_lo[(size_t)2 * B_ * G_ * HID_];
// g_f stored contiguously as [row 512][g][o] (de-interleaved; Wg1 rows permuted instead)
__device__ __half g_f_hi[(size_t)2 * B_ * G_ * FEAT_];
__device__ __half g_f_lo[(size_t)2 * B_ * G_ * FEAT_];
__device__ float  g_part[(size_t)NSPL * 2 * B_ * HID_];
__device__ float  g_part4[(size_t)NSPL4 * 2 * B_ * FEAT_];
__device__ __half g_hg_hi[(size_t)2 * B_ * HID_];
__device__ __half g_hg_lo[(size_t)2 * B_ * HID_];
__device__ float  g_scores[B_];

__device__ __forceinline__ float silu_f(float v) {
    return v / (1.0f + __expf(-v));
}
__device__ __forceinline__ uint32_t smem_to_u32(const void* p) {
    uint32_t a;
    asm("{ .reg .u64 t; cvta.to.shared.u64 t, %1; cvt.u32.u64 %0, t; }"
        : "=r"(a) : "l"(p));
    return a;
}

// ---- family-portable primitives (valid on compute_103) ----
__device__ __forceinline__ void ldsm_x4(uint32_t* r, uint32_t addr) {
    asm volatile("ldmatrix.sync.aligned.m8n8.x4.shared.b16 {%0,%1,%2,%3}, [%4];"
        : "=r"(r[0]), "=r"(r[1]), "=r"(r[2]), "=r"(r[3]) : "r"(addr));
}
// x4 trans: 16 k-rows x 16 n -> two adjacent-nt B fragments
__device__ __forceinline__ void ldsm_x4t(uint32_t* r, uint32_t addr) {
    asm volatile("ldmatrix.sync.aligned.m8n8.x4.trans.shared.b16 {%0,%1,%2,%3}, [%4];"
        : "=r"(r[0]), "=r"(r[1]), "=r"(r[2]), "=r"(r[3]) : "r"(addr));
}
__device__ __forceinline__ void mma_f32(float* d, const uint32_t* a, const uint32_t* b) {
    asm volatile(
        "mma.sync.aligned.m16n8k16.row.col.f32.f16.f16.f32 "
        "{%0,%1,%2,%3}, {%4,%5,%6,%7}, {%8,%9}, {%0,%1,%2,%3};"
        : "+f"(d[0]), "+f"(d[1]), "+f"(d[2]), "+f"(d[3])
        : "r"(a[0]), "r"(a[1]), "r"(a[2]), "r"(a[3]), "r"(b[0]), "r"(b[1]));
}
__device__ __forceinline__ void mma_f16(uint32_t* d, const uint32_t* a, const uint32_t* b) {
    asm volatile(
        "mma.sync.aligned.m16n8k16.row.col.f16.f16.f16.f16 "
        "{%0,%1}, {%2,%3,%4,%5}, {%6,%7}, {%0,%1};"
        : "+r"(d[0]), "+r"(d[1])
        : "r"(a[0]), "r"(a[1]), "r"(a[2]), "r"(a[3]), "r"(b[0]), "r"(b[1]));
}
// L2-only async copy (no L1 allocation) — A planes are single-use streams
__device__ __forceinline__ void cp_async16_cg(uint32_t dst, const void* src) {
    asm volatile("cp.async.cg.shared.global [%0], [%1], 16;" :: "r"(dst), "l"(src));
}
__device__ __forceinline__ void cp_async_commit() {
    asm volatile("cp.async.commit_group;" ::: "memory");
}
__device__ __forceinline__ void cp_async_wait0() {
    asm volatile("cp.async.wait_group 0;" ::: "memory");
}

__device__ __forceinline__ void split_f32(float x, __half& hi, __half& lo) {
    hi = __float2half_rn(x);
    lo = __float2half_rn(x - __half2float(hi));
}
__device__ __forceinline__ void split_store2(__half* hi, __half* lo, float v0, float v1) {
    __half h0, l0, h1, l1;
    split_f32(v0, h0, l0); split_f32(v1, h1, l1);
    *reinterpret_cast<__half2*>(hi) = __halves2half2(h0, h1);
    *reinterpret_cast<__half2*>(lo) = __halves2half2(l0, l1);
}
__device__ __forceinline__ void split4(const float* v, uint32_t* hi2, uint32_t* lo2) {
    __half h0,l0,h1,l1,h2,l2,h3,l3;
    split_f32(v[0], h0, l0); split_f32(v[1], h1, l1);
    split_f32(v[2], h2, l2); split_f32(v[3], h3, l3);
    __half2 a = __halves2half2(h0, h1), b = __halves2half2(h2, h3);
    __half2 c = __halves2half2(l0, l1), d = __halves2half2(l2, l3);
    hi2[0] = *reinterpret_cast<uint32_t*>(&a);
    hi2[1] = *reinterpret_cast<uint32_t*>(&b);
    lo2[0] = *reinterpret_cast<uint32_t*>(&c);
    lo2[1] = *reinterpret_cast<uint32_t*>(&d);
}

// ---------------- GEMM body (512 threads, warp grid 4x4, 32x32/warp, BK=64) ----
// A pre-split hi/lo half planes (row stride lda halves, zero-padded past K).
// PERM: B row = (k + koff)*G_ + gsel (gf1). FULLK: K % 64 == 0 (no tail guard).
template<bool PERM, bool FULLK>
__device__ __forceinline__ void gemm_body(
    const __half* __restrict__ Ah, const __half* __restrict__ Al, int lda,
    const float* __restrict__ W, int ldw,
    int K, int m0, int n0, float acc[2][4][4],
    int koff = 0, int gsel = 0)
{
    extern __shared__ char dyn[];
    const uint32_t sb = smem_to_u32(dyn);

    const int tid  = threadIdx.x;
    const int lane = tid & 31;
    const int wid  = tid >> 5;
    const int wm   = (wid >> 2) * 32;
    const int wn   = (wid & 3) * 32;

    const int ar = tid >> 2;
    const int as = (tid & 3) << 4;
    const int kr = tid >> 3;
    const int nb = (tid & 7) << 4;

    const int nk = (K + BK - 1) / BK;

    uint32_t accc[2][4][2];
    #pragma unroll
    for (int mt = 0; mt < 2; ++mt)
        #pragma unroll
        for (int nt = 0; nt < 4; ++nt) {
            accc[mt][nt][0] = 0u; accc[mt][nt][1] = 0u;
            #pragma unroll
            for (int e = 0; e < 4; ++e) acc[mt][nt][e] = 0.0f;
        }

    float rb[16];

    auto cpA = [&](int k0, int buf) {
        const uint32_t d = sb + buf * BUF_BYTES + (uint32_t)(ar * BKP + as) * 2;
        const size_t go = (size_t)(m0 + ar) * lda + k0 + as;
        cp_async16_cg(d + PB_AHI,      Ah + go);
        cp_async16_cg(d + PB_AHI + 16, Ah + go + 8);
        cp_async16_cg(d + PB_ALO,      Al + go);
        cp_async16_cg(d + PB_ALO + 16, Al + go + 8);
    };
    auto ldgB = [&](int k0) {
        const int kgB = k0 + kr;
        if (kgB < K) {
            const size_t row = PERM ? ((size_t)(kgB + koff) * G_ + gsel)
                                    : (size_t)kgB;
            const float4* Wp = reinterpret_cast<const float4*>(W + row * ldw + n0 + nb);
            #pragma unroll
            for (int i = 0; i < 4; ++i) {
                float4 v = __ldcs(Wp + i);     // evict-first: weights are single-use
                rb[i*4+0] = v.x; rb[i*4+1] = v.y; rb[i*4+2] = v.z; rb[i*4+3] = v.w;
            }
        } else {
            #pragma unroll
            for (int i = 0; i < 16; ++i) rb[i] = 0.0f;
        }
    };
    auto stB = [&](int buf) {
        char* base = dyn + buf * BUF_BYTES;
        uint32_t hi2[4], lo2[4];
        split4(rb,     hi2,     lo2);
        split4(rb + 4, hi2 + 2, lo2 + 2);
        *reinterpret_cast<uint4*>(base + PB_BHI + (kr*BNP + nb)*2) =
            make_uint4(hi2[0], hi2[1], hi2[2], hi2[3]);
        *reinterpret_cast<uint4*>(base + PB_BLO + (kr*BNP + nb)*2) =
            make_uint4(lo2[0], lo2[1], lo2[2], lo2[3]);
        split4(rb + 8,  hi2,     lo2);
        split4(rb + 12, hi2 + 2, lo2 + 2);
        *reinterpret_cast<uint4*>(base + PB_BHI + (kr*BNP + nb + 8)*2) =
            make_uint4(hi2[0], hi2[1], hi2[2], hi2[3]);
        *reinterpret_cast<uint4*>(base + PB_BLO + (kr*BNP + nb + 8)*2) =
            make_uint4(lo2[0], lo2[1], lo2[2], lo2[3]);
    };

    // prologue
    cpA(0, 0);
    ldgB(0);
    stB(0);
    cp_async_commit();
    cp_async_wait0();
    __syncthreads();

    for (int t = 0; t < nk; ++t) {
        const int cur = t & 1, nxt = (t + 1) & 1;
        const bool more = (t + 1) < nk;
        const int k0 = t * BK;

        if (more) {
            cpA((t + 1) * BK, nxt);
            cp_async_commit();
            ldgB((t + 1) * BK);
        }

        {
            const uint32_t aHiB = sb + cur * BUF_BYTES + PB_AHI;
            const uint32_t aLoB = sb + cur * BUF_BYTES + PB_ALO;
            const uint32_t bHiB = sb + cur * BUF_BYTES + PB_BHI;
            const uint32_t bLoB = sb + cur * BUF_BYTES + PB_BLO;
            const int l = lane & 15;
            const int ks_end = FULLK ? 4 : min(4, (K - k0 + 15) >> 4);
            #pragma unroll
            for (int ks = 0; ks < 4; ++ks) {
                if (!FULLK && ks >= ks_end) break;

                uint32_t bh[4][2];
                #pragma unroll
                for (int ntp = 0; ntp < 2; ++ntp) {
                    const uint32_t off =
                        ((uint32_t)(ks * 16 + l) * BNP + wn + ntp * 16 + (lane >> 4) * 8) * 2;
                    uint32_t r4[4];
                    ldsm_x4t(r4, bHiB + off);
                    bh[ntp*2][0] = r4[0]; bh[ntp*2][1] = r4[1];
                    bh[ntp*2+1][0] = r4[2]; bh[ntp*2+1][1] = r4[3];
                }
                uint32_t ah[2][4];
                #pragma unroll
                for (int mt = 0; mt < 2; ++mt) {
                    const uint32_t offa =
                        ((uint32_t)(wm + mt * 16 + l) * BKP + ks * 16 + (lane >> 4) * 8) * 2;
                    ldsm_x4(ah[mt], aHiB + offa);
                }
                #pragma unroll
                for (int mt = 0; mt < 2; ++mt)
                    #pragma unroll
                    for (int nt = 0; nt < 4; ++nt)
                        mma_f32(acc[mt][nt], ah[mt], bh[nt]);

                uint32_t bl[4][2];
                #pragma unroll
                for (int ntp = 0; ntp < 2; ++ntp) {
                    const uint32_t off =
                        ((uint32_t)(ks * 16 + l) * BNP + wn + ntp * 16 + (lane >> 4) * 8) * 2;
                    uint32_t r4[4];
                    ldsm_x4t(r4, bLoB + off);
                    bl[ntp*2][0] = r4[0]; bl[ntp*2][1] = r4[1];
                    bl[ntp*2+1][0] = r4[2]; bl[ntp*2+1][1] = r4[3];
                }
                #pragma unroll
                for (int mt = 0; mt < 2; ++mt)
                    #pragma unroll
                    for (int nt = 0; nt < 4; ++nt)
                        mma_f16(accc[mt][nt], ah[mt], bl[nt]);

                uint32_t al[2][4];
                #pragma unroll
                for (int mt = 0; mt < 2; ++mt) {
                    const uint32_t offa =
                        ((uint32_t)(wm + mt * 16 + l) * BKP + ks * 16 + (lane >> 4) * 8) * 2;
                    ldsm_x4(al[mt], aLoB + offa);
                }
                #pragma unroll
                for (int mt = 0; mt < 2; ++mt)
                    #pragma unroll
                    for (int nt = 0; nt < 4; ++nt)
                        mma_f16(accc[mt][nt], al[mt], bh[nt]);
            }
        }

        if (more) {
            stB(nxt);
            cp_async_wait0();
        }
        __syncthreads();
    }

    #pragma unroll
    for (int mt = 0; mt < 2; ++mt)
        #pragma unroll
        for (int nt = 0; nt < 4; ++nt) {
            const __half2 c01 = *reinterpret_cast<const __half2*>(&accc[mt][nt][0]);
            const __half2 c23 = *reinterpret_cast<const __half2*>(&accc[mt][nt][1]);
            acc[mt][nt][0] += __low2float(c01);
            acc[mt][nt][1] += __high2float(c01);
            acc[mt][nt][2] += __low2float(c23);
            acc[mt][nt][3] += __high2float(c23);
        }
}

// ================= pre-pass: split q,k into padded hi/lo planes =================
__global__ void __launch_bounds__(128) k_split_qk(
    const float* __restrict__ q, const float* __restrict__ k)
{
    const int g = blockIdx.x, b = blockIdx.y, br = blockIdx.z;
    const int tid = threadIdx.x;
    const float* src = (br ? k : q) + (size_t)b * (G_ * GS_) + g * GS_;
    const size_t base = ((size_t)(br * G_ + g) * B_ + b) * GSP;
    for (int i = tid; i < GSP; i += 128) {
        const float x = (i < GS_) ? src[i] : 0.0f;
        __half h, l;
        split_f32(x, h, l);
        g_qk_hi[base + i] = h;
        g_qk_lo[base + i] = l;
    }
}

// ================= stage kernels =================

// stage 1: grouped fc1. grid (2, 8, 32)
__global__ void __launch_bounds__(THREADS, 1) k_fc1g(
    const float* __restrict__ Wq1, const float* __restrict__ bq1,
    const float* __restrict__ Wk1, const float* __restrict__ bk1)
{
    const int z = blockIdx.z, br = z >> 4, g = z & 15;
    const int m0 = blockIdx.x * BM, n0 = blockIdx.y * BN;

    const size_t abase = (size_t)(br * G_ + g) * B_ * GSP;
    const float* W    = (br ? Wk1 : Wq1) + (size_t)g * GS_ * HID_;
    const float* bias = (br ? bk1 : bq1) + g * HID_;

    float acc[2][4][4];
    gemm_body<false, false>(g_qk_hi + abase, g_qk_lo + abase, GSP, W, HID_, GS_, m0, n0, acc);

    const int lane = threadIdx.x & 31, wid = threadIdx.x >> 5;
    const int wm = (wid >> 2) * 32, wn = (wid & 3) * 32;
    #pragma unroll
    for (int mt = 0; mt < 2; ++mt) {
        const int r = m0 + wm + mt * 16 + (lane >> 2);
        #pragma unroll
        for (int nt = 0; nt < 4; ++nt) {
            const int c = n0 + wn + nt * 8 + (lane & 3) * 2;
            const float b0 = bias[c], b1 = bias[c + 1];
            const size_t i0 = (size_t)(br * B_ + r) * (G_ * HID_) + (size_t)g * HID_ + c;
            const size_t i1 = i0 + (size_t)8 * (G_ * HID_);
            split_store2(&g_h_hi[i0], &g_h_lo[i0],
                         silu_f(acc[mt][nt][0] + b0), silu_f(acc[mt][nt][1] + b1));
            split_store2(&g_h_hi[i1], &g_h_lo[i1],
                         silu_f(acc[mt][nt][2] + b0), silu_f(acc[mt][nt][3] + b1));
        }
    }
}

// stage 2: grouped fc4, contiguous [row][g][o] store. grid (2, 16, 32)
__global__ void __launch_bounds__(THREADS, 1) k_fc4g(
    const float* __restrict__ Wq4, const float* __restrict__ bq4,
    const float* __restrict__ Wk4, const float* __restrict__ bk4)
{
    const int z = blockIdx.z, br = z >> 4, g = z & 15;
    const int m0 = blockIdx.x * BM, n0 = blockIdx.y * BN;

    const __half* Ah  = g_h_hi + (size_t)br * B_ * G_ * HID_ + (size_t)g * HID_;
    const __half* Al  = g_h_lo + (size_t)br * B_ * G_ * HID_ + (size_t)g * HID_;
    const float* W    = (br ? Wk4 : Wq4) + (size_t)g * HID_ * FEAT_;
    const float* bias = (br ? bk4 : bq4) + g * FEAT_;

    float acc[2][4][4];
    gemm_body<false, true>(Ah, Al, G_ * HID_, W, FEAT_, HID_, m0, n0, acc);

    const int lane = threadIdx.x & 31, wid = threadIdx.x >> 5;
    const int wm = (wid >> 2) * 32, wn = (wid & 3) * 32;
    #pragma unroll
    for (int mt = 0; mt < 2; ++mt) {
        const int r = m0 + wm + mt * 16 + (lane >> 2);
        const size_t rb0 = (size_t)(br * B_ + r)     * (G_ * FEAT_) + (size_t)g * FEAT_;
        const size_t rb1 = (size_t)(br * B_ + r + 8) * (G_ * FEAT_) + (size_t)g * FEAT_;
        #pragma unroll
        for (int nt = 0; nt < 4; ++nt) {
            const int c = n0 + wn + nt * 8 + (lane & 3) * 2;
            const float b0 = bias[c], b1 = bias[c + 1];
            split_store2(&g_f_hi[rb0 + c], &g_f_lo[rb0 + c],
                         silu_f(acc[mt][nt][0] + b0), silu_f(acc[mt][nt][1] + b1));
            split_store2(&g_f_hi[rb1 + c], &g_f_lo[rb1 + c],
                         silu_f(acc[mt][nt][2] + b0), silu_f(acc[mt][nt][3] + b1));
        }
    }
}

// stage 3: global fc1 split-K with permuted weight rows. grid (4, 8, NSPL=32)
__global__ void __launch_bounds__(THREADS, 1) k_gf1(const float* __restrict__ Wg1)
{
    const int s = blockIdx.z;
    const int m0 = blockIdx.x * BM, n0 = blockIdx.y * BN;

    const __half* Ah = g_f_hi + (size_t)s * KSPL;
    const __half* Al = g_f_lo + (size_t)s * KSPL;
    const int koff = (s & 1) * KSPL;
    const int gsel = s >> 1;

    float acc[2][4][4];
    gemm_body<true, true>(Ah, Al, G_ * FEAT_, Wg1, HID_, KSPL, m0, n0, acc, koff, gsel);

    const int lane = threadIdx.x & 31, wid = threadIdx.x >> 5;
    const int wm = (wid >> 2) * 32, wn = (wid & 3) * 32;
    float* P = g_part + (size_t)s * (2 * B_ * HID_);
    #pragma unroll
    for (int mt = 0; mt < 2; ++mt) {
        const int r = m0 + wm + mt * 16 + (lane >> 2);
        #pragma unroll
        for (int nt = 0; nt < 4; ++nt) {
            const int c = n0 + wn + nt * 8 + (lane & 3) * 2;
            __stcs(&P[(size_t)r * HID_ + c],           acc[mt][nt][0]);
            __stcs(&P[(size_t)r * HID_ + c + 1],       acc[mt][nt][1]);
            __stcs(&P[(size_t)(r + 8) * HID_ + c],     acc[mt][nt][2]);
            __stcs(&P[(size_t)(r + 8) * HID_ + c + 1], acc[mt][nt][3]);
        }
    }
}

// reduce NSPL partials + bias + silu -> pre-split g_hg
__global__ void __launch_bounds__(256) k_reduce_silu(const float* __restrict__ bg1)
{
    const int idx = blockIdx.x * blockDim.x + threadIdx.x;
    if (idx >= 2 * B_ * HID_) return;
    const int col = idx & (HID_ - 1);
    float v = bg1[col];
    #pragma unroll
    for (int s = 0; s < NSPL; ++s)
        v += __ldcs(&g_part[(size_t)s * (2 * B_ * HID_) + idx]);
    v = silu_f(v);
    __half h, l;
    split_f32(v, h, l);
    g_hg_hi[idx] = h;
    g_hg_lo[idx] = l;
}

// stage 4: global fc4 split-K. grid (4, 16, NSPL4=8)
__global__ void __launch_bounds__(THREADS, 1) k_gf4(const float* __restrict__ Wg4)
{
    const int s = blockIdx.z;
    const int m0 = blockIdx.x * BM, n0 = blockIdx.y * BN;

    const __half* Ah = g_hg_hi + (size_t)s * KSPL4;
    const __half* Al = g_hg_lo + (size_t)s * KSPL4;
    const float*  W  = Wg4 + (size_t)s * KSPL4 * FEAT_;

    float acc[2][4][4];
    gemm_body<false, true>(Ah, Al, HID_, W, FEAT_, KSPL4, m0, n0, acc);

    const int lane = threadIdx.x & 31, wid = threadIdx.x >> 5;
    const int wm = (wid >> 2) * 32, wn = (wid & 3) * 32;
    float* P = g_part4 + (size_t)s * (2 * B_ * FEAT_);
    #pragma unroll
    for (int mt = 0; mt < 2; ++mt) {
        const int r = m0 + wm + mt * 16 + (lane >> 2);
        #pragma unroll
        for (int nt = 0; nt < 4; ++nt) {
            const int c = n0 + wn + nt * 8 + (lane & 3) * 2;
            __stcs(&P[(size_t)r * FEAT_ + c],           acc[mt][nt][0]);
            __stcs(&P[(size_t)r * FEAT_ + c + 1],       acc[mt][nt][1]);
            __stcs(&P[(size_t)(r + 8) * FEAT_ + c],     acc[mt][nt][2]);
            __stcs(&P[(size_t)(r + 8) * FEAT_ + c + 1], acc[mt][nt][3]);
        }
    }
}

// fused: reduce NSPL4 partials + bias + silu for q&k rows, dot, store score. grid (B_)
__global__ void __launch_bounds__(256) k_reduce4_dot(const float* __restrict__ bg4)
{
    const int b = blockIdx.x, t = threadIdx.x;
    float s = 0.0f;
    for (int col = t; col < FEAT_; col += 256) {
        float vq = bg4[col];
        float vk = vq;
        #pragma unroll
        for (int sp = 0; sp < NSPL4; ++sp) {
            const float* P = g_part4 + (size_t)sp * (2 * B_ * FEAT_);
            vq += __ldcs(&P[(size_t)b * FEAT_ + col]);
            vk += __ldcs(&P[(size_t)(B_ + b) * FEAT_ + col]);
        }
        s = fmaf(silu_f(vq), silu_f(vk), s);
    }
    __shared__ float sh[256];
    sh[t] = s;
    __syncthreads();
    for (int off = 128; off > 0; off >>= 1) {
        if (t < off) sh[t] += sh[t + off];
        __syncthreads();
    }
    if (t == 0) g_scores[b] = sh[0];
}

// softmax over batch
__global__ void __launch_bounds__(256) k_softmax(float* __restrict__ out)
{
    const int t = threadIdx.x;
    __shared__ float sh[256];
    float v = g_scores[t];
    sh[t] = v;
    __syncthreads();
    for (int off = 128; off > 0; off >>= 1) {
        if (t < off) sh[t] = fmaxf(sh[t], sh[t + off]);
        __syncthreads();
    }
    const float m = sh[0];
    __syncthreads();
    const float e = expf(v - m);
    sh[t] = e;
    __syncthreads();
    for (int off = 128; off > 0; off >>= 1) {
        if (t < off) sh[t] += sh[t + off];
        __syncthreads();
    }
    out[t] = e / sh[0];
}

// ================= launch =================
extern "C" void kernel_launch(void* const* d_in, const int* in_sizes, int n_in,
                              void* d_out, int out_size)
{
    const float* q   = (const float*)d_in[0];
    const float* k   = (const float*)d_in[1];
    const float* Wq1 = (const float*)d_in[2];
    const float* bq1 = (const float*)d_in[3];
    const float* Wq4 = (const float*)d_in[4];
    const float* bq4 = (const float*)d_in[5];
    const float* Wk1 = (const float*)d_in[6];
    const float* bk1 = (const float*)d_in[7];
    const float* Wk4 = (const float*)d_in[8];
    const float* bk4 = (const float*)d_in[9];
    const float* Wg1 = (const float*)d_in[10];
    const float* bg1 = (const float*)d_in[11];
    const float* Wg4 = (const float*)d_in[12];
    const float* bg4 = (const float*)d_in[13];
    float* out = (float*)d_out;

    cudaFuncSetAttribute(k_fc1g, cudaFuncAttributeMaxDynamicSharedMemorySize, SMEM_TOTAL);
    cudaFuncSetAttribute(k_fc4g, cudaFuncAttributeMaxDynamicSharedMemorySize, SMEM_TOTAL);
    cudaFuncSetAttribute(k_gf1,  cudaFuncAttributeMaxDynamicSharedMemorySize, SMEM_TOTAL);
    cudaFuncSetAttribute(k_gf4,  cudaFuncAttributeMaxDynamicSharedMemorySize, SMEM_TOTAL);

    k_split_qk<<<dim3(G_, B_, 2), 128>>>(q, k);
    k_fc1g<<<dim3(2, 8, 2 * G_),   THREADS, SMEM_TOTAL>>>(Wq1, bq1, Wk1, bk1);
    k_fc4g<<<dim3(2, 16, 2 * G_),  THREADS, SMEM_TOTAL>>>(Wq4, bq4, Wk4, bk4);
    k_gf1<<<dim3(4, 8, NSPL),      THREADS, SMEM_TOTAL>>>(Wg1);
    k_reduce_silu<<<(2 * B_ * HID_) / 256, 256>>>(bg1);
    k_gf4<<<dim3(4, 16, NSPL4),    THREADS, SMEM_TOTAL>>>(Wg4);
    k_reduce4_dot<<<B_, 256>>>(bg4);
    k_softmax<<<1, 256>>>(out);
}

// round 17
// speedup vs baseline: 1.0497x; 1.0497x over previous
#include <cuda_runtime.h>
#include <cuda_fp16.h>
#include <math.h>
#include <stdint.h>

#define B_    256
#define G_    16
#define GS_   588
#define GSP   640
#define HID_  1024
#define FEAT_ 2048
#define NSPL  32
#define KSPL  ((G_ * FEAT_) / NSPL)   // 1024
#define NSPL4 8
#define KSPL4 (HID_ / NSPL4)          // 128

#define THREADS 512
#define BM 128
#define BN 128
#define BK 64
#define BKP 72     // padded A row (halves): 144B stride, conflict-free LDSM
#define BNP 136    // padded B row (halves): 272B stride, conflict-free LDSM

// per-buffer SMEM layout (bytes)
#define PB_AHI 0
#define PB_ALO 18432
#define PB_BHI 36864
#define PB_BLO 54272
#define BUF_BYTES 71680
#define SMEM_TOTAL (2 * BUF_BYTES)   // 143360

// ---------------- scratch (device globals) ----------------
__device__ __half g_qk_hi[(size_t)2 * G_ * B_ * GSP];
__device__ __half g_qk_lo[(size_t)2 * G_ * B_ * GSP];
__device__ __half g_h_hi[(size_t)2 * B_ * G_ * HID_];
__device__ __half g_h_lo[(size_t)2 * B_ * G_ * HID_];
// g_f stored contiguously as [row 512][g][o] (de-interleaved; Wg1 rows permuted instead)
__device__ __half g_f_hi[(size_t)2 * B_ * G_ * FEAT_];
__device__ __half g_f_lo[(size_t)2 * B_ * G_ * FEAT_];
__device__ float  g_part[(size_t)NSPL * 2 * B_ * HID_];
__device__ float  g_part4[(size_t)NSPL4 * 2 * B_ * FEAT_];
__device__ __half g_hg_hi[(size_t)2 * B_ * HID_];
__device__ __half g_hg_lo[(size_t)2 * B_ * HID_];
__device__ float  g_scores[B_];

__device__ __forceinline__ float silu_f(float v) {
    return v / (1.0f + __expf(-v));
}
__device__ __forceinline__ uint32_t smem_to_u32(const void* p) {
    uint32_t a;
    asm("{ .reg .u64 t; cvta.to.shared.u64 t, %1; cvt.u32.u64 %0, t; }"
        : "=r"(a) : "l"(p));
    return a;
}

// ---- family-portable primitives (valid on compute_103) ----
__device__ __forceinline__ void ldsm_x4(uint32_t* r, uint32_t addr) {
    asm volatile("ldmatrix.sync.aligned.m8n8.x4.shared.b16 {%0,%1,%2,%3}, [%4];"
        : "=r"(r[0]), "=r"(r[1]), "=r"(r[2]), "=r"(r[3]) : "r"(addr));
}
// x4 trans: 16 k-rows x 16 n -> two adjacent-nt B fragments
__device__ __forceinline__ void ldsm_x4t(uint32_t* r, uint32_t addr) {
    asm volatile("ldmatrix.sync.aligned.m8n8.x4.trans.shared.b16 {%0,%1,%2,%3}, [%4];"
        : "=r"(r[0]), "=r"(r[1]), "=r"(r[2]), "=r"(r[3]) : "r"(addr));
}
__device__ __forceinline__ void mma_f32(float* d, const uint32_t* a, const uint32_t* b) {
    asm volatile(
        "mma.sync.aligned.m16n8k16.row.col.f32.f16.f16.f32 "
        "{%0,%1,%2,%3}, {%4,%5,%6,%7}, {%8,%9}, {%0,%1,%2,%3};"
        : "+f"(d[0]), "+f"(d[1]), "+f"(d[2]), "+f"(d[3])
        : "r"(a[0]), "r"(a[1]), "r"(a[2]), "r"(a[3]), "r"(b[0]), "r"(b[1]));
}
__device__ __forceinline__ void mma_f16(uint32_t* d, const uint32_t* a, const uint32_t* b) {
    asm volatile(
        "mma.sync.aligned.m16n8k16.row.col.f16.f16.f16.f16 "
        "{%0,%1}, {%2,%3,%4,%5}, {%6,%7}, {%0,%1};"
        : "+r"(d[0]), "+r"(d[1])
        : "r"(a[0]), "r"(a[1]), "r"(a[2]), "r"(a[3]), "r"(b[0]), "r"(b[1]));
}
__device__ __forceinline__ void cp_async16(uint32_t dst, const void* src) {
    asm volatile("cp.async.ca.shared.global [%0], [%1], 16;" :: "r"(dst), "l"(src));
}
__device__ __forceinline__ void cp_async_commit() {
    asm volatile("cp.async.commit_group;" ::: "memory");
}
__device__ __forceinline__ void cp_async_wait0() {
    asm volatile("cp.async.wait_group 0;" ::: "memory");
}

__device__ __forceinline__ void split_f32(float x, __half& hi, __half& lo) {
    hi = __float2half_rn(x);
    lo = __float2half_rn(x - __half2float(hi));
}
__device__ __forceinline__ void split_store2(__half* hi, __half* lo, float v0, float v1) {
    __half h0, l0, h1, l1;
    split_f32(v0, h0, l0); split_f32(v1, h1, l1);
    *reinterpret_cast<__half2*>(hi) = __halves2half2(h0, h1);
    *reinterpret_cast<__half2*>(lo) = __halves2half2(l0, l1);
}
__device__ __forceinline__ void split4(const float* v, uint32_t* hi2, uint32_t* lo2) {
    __half h0,l0,h1,l1,h2,l2,h3,l3;
    split_f32(v[0], h0, l0); split_f32(v[1], h1, l1);
    split_f32(v[2], h2, l2); split_f32(v[3], h3, l3);
    __half2 a = __halves2half2(h0, h1), b = __halves2half2(h2, h3);
    __half2 c = __halves2half2(l0, l1), d = __halves2half2(l2, l3);
    hi2[0] = *reinterpret_cast<uint32_t*>(&a);
    hi2[1] = *reinterpret_cast<uint32_t*>(&b);
    lo2[0] = *reinterpret_cast<uint32_t*>(&c);
    lo2[1] = *reinterpret_cast<uint32_t*>(&d);
}

// ---------------- GEMM body (512 threads, warp grid 4x4, 32x32/warp, BK=64) ----
// A pre-split hi/lo half planes (row stride lda halves, zero-padded past K).
// PERM: B row = (k + koff)*G_ + gsel (gf1). FULLK: K % 64 == 0 (no tail guard).
template<bool PERM, bool FULLK>
__device__ __forceinline__ void gemm_body(
    const __half* __restrict__ Ah, const __half* __restrict__ Al, int lda,
    const float* __restrict__ W, int ldw,
    int K, int m0, int n0, float acc[2][4][4],
    int koff = 0, int gsel = 0)
{
    extern __shared__ char dyn[];
    const uint32_t sb = smem_to_u32(dyn);

    const int tid  = threadIdx.x;
    const int lane = tid & 31;
    const int wid  = tid >> 5;
    const int wm   = (wid >> 2) * 32;
    const int wn   = (wid & 3) * 32;

    const int ar = tid >> 2;
    const int as = (tid & 3) << 4;
    const int kr = tid >> 3;
    const int nb = (tid & 7) << 4;

    const int nk = (K + BK - 1) / BK;

    uint32_t accc[2][4][2];
    #pragma unroll
    for (int mt = 0; mt < 2; ++mt)
        #pragma unroll
        for (int nt = 0; nt < 4; ++nt) {
            accc[mt][nt][0] = 0u; accc[mt][nt][1] = 0u;
            #pragma unroll
            for (int e = 0; e < 4; ++e) acc[mt][nt][e] = 0.0f;
        }

    float rb[16];

    auto cpA = [&](int k0, int buf) {
        const uint32_t d = sb + buf * BUF_BYTES + (uint32_t)(ar * BKP + as) * 2;
        const size_t go = (size_t)(m0 + ar) * lda + k0 + as;
        cp_async16(d + PB_AHI,      Ah + go);
        cp_async16(d + PB_AHI + 16, Ah + go + 8);
        cp_async16(d + PB_ALO,      Al + go);
        cp_async16(d + PB_ALO + 16, Al + go + 8);
    };
    auto ldgB = [&](int k0) {
        const int kgB = k0 + kr;
        if (kgB < K) {
            const size_t row = PERM ? ((size_t)(kgB + koff) * G_ + gsel)
                                    : (size_t)kgB;
            const float* Wp = W + row * ldw + n0 + nb;
            #pragma unroll
            for (int i = 0; i < 4; ++i) {
                float4 v = *reinterpret_cast<const float4*>(Wp + i * 4);
                rb[i*4+0] = v.x; rb[i*4+1] = v.y; rb[i*4+2] = v.z; rb[i*4+3] = v.w;
            }
        } else {
            #pragma unroll
            for (int i = 0; i < 16; ++i) rb[i] = 0.0f;
        }
    };
    auto stB = [&](int buf) {
        char* base = dyn + buf * BUF_BYTES;
        uint32_t hi2[4], lo2[4];
        split4(rb,     hi2,     lo2);
        split4(rb + 4, hi2 + 2, lo2 + 2);
        *reinterpret_cast<uint4*>(base + PB_BHI + (kr*BNP + nb)*2) =
            make_uint4(hi2[0], hi2[1], hi2[2], hi2[3]);
        *reinterpret_cast<uint4*>(base + PB_BLO + (kr*BNP + nb)*2) =
            make_uint4(lo2[0], lo2[1], lo2[2], lo2[3]);
        split4(rb + 8,  hi2,     lo2);
        split4(rb + 12, hi2 + 2, lo2 + 2);
        *reinterpret_cast<uint4*>(base + PB_BHI + (kr*BNP + nb + 8)*2) =
            make_uint4(hi2[0], hi2[1], hi2[2], hi2[3]);
        *reinterpret_cast<uint4*>(base + PB_BLO + (kr*BNP + nb + 8)*2) =
            make_uint4(lo2[0], lo2[1], lo2[2], lo2[3]);
    };

    // prologue
    cpA(0, 0);
    ldgB(0);
    stB(0);
    cp_async_commit();
    cp_async_wait0();
    __syncthreads();

    for (int t = 0; t < nk; ++t) {
        const int cur = t & 1, nxt = (t + 1) & 1;
        const bool more = (t + 1) < nk;
        const int k0 = t * BK;

        if (more) {
            cpA((t + 1) * BK, nxt);
            cp_async_commit();
            ldgB((t + 1) * BK);
        }

        {
            const uint32_t aHiB = sb + cur * BUF_BYTES + PB_AHI;
            const uint32_t aLoB = sb + cur * BUF_BYTES + PB_ALO;
            const uint32_t bHiB = sb + cur * BUF_BYTES + PB_BHI;
            const uint32_t bLoB = sb + cur * BUF_BYTES + PB_BLO;
            const int l = lane & 15;
            const int ks_end = FULLK ? 4 : min(4, (K - k0 + 15) >> 4);
            #pragma unroll
            for (int ks = 0; ks < 4; ++ks) {
                if (!FULLK && ks >= ks_end) break;

                uint32_t bh[4][2];
                #pragma unroll
                for (int ntp = 0; ntp < 2; ++ntp) {
                    const uint32_t off =
                        ((uint32_t)(ks * 16 + l) * BNP + wn + ntp * 16 + (lane >> 4) * 8) * 2;
                    uint32_t r4[4];
                    ldsm_x4t(r4, bHiB + off);
                    bh[ntp*2][0] = r4[0]; bh[ntp*2][1] = r4[1];
                    bh[ntp*2+1][0] = r4[2]; bh[ntp*2+1][1] = r4[3];
                }
                uint32_t ah[2][4];
                #pragma unroll
                for (int mt = 0; mt < 2; ++mt) {
                    const uint32_t offa =
                        ((uint32_t)(wm + mt * 16 + l) * BKP + ks * 16 + (lane >> 4) * 8) * 2;
                    ldsm_x4(ah[mt], aHiB + offa);
                }
                #pragma unroll
                for (int mt = 0; mt < 2; ++mt)
                    #pragma unroll
                    for (int nt = 0; nt < 4; ++nt)
                        mma_f32(acc[mt][nt], ah[mt], bh[nt]);

                uint32_t bl[4][2];
                #pragma unroll
                for (int ntp = 0; ntp < 2; ++ntp) {
                    const uint32_t off =
                        ((uint32_t)(ks * 16 + l) * BNP + wn + ntp * 16 + (lane >> 4) * 8) * 2;
                    uint32_t r4[4];
                    ldsm_x4t(r4, bLoB + off);
                    bl[ntp*2][0] = r4[0]; bl[ntp*2][1] = r4[1];
                    bl[ntp*2+1][0] = r4[2]; bl[ntp*2+1][1] = r4[3];
                }
                #pragma unroll
                for (int mt = 0; mt < 2; ++mt)
                    #pragma unroll
                    for (int nt = 0; nt < 4; ++nt)
                        mma_f16(accc[mt][nt], ah[mt], bl[nt]);

                uint32_t al[2][4];
                #pragma unroll
                for (int mt = 0; mt < 2; ++mt) {
                    const uint32_t offa =
                        ((uint32_t)(wm + mt * 16 + l) * BKP + ks * 16 + (lane >> 4) * 8) * 2;
                    ldsm_x4(al[mt], aLoB + offa);
                }
                #pragma unroll
                for (int mt = 0; mt < 2; ++mt)
                    #pragma unroll
                    for (int nt = 0; nt < 4; ++nt)
                        mma_f16(accc[mt][nt], al[mt], bh[nt]);
            }
        }

        if (more) {
            stB(nxt);
            cp_async_wait0();
        }
        __syncthreads();
    }

    #pragma unroll
    for (int mt = 0; mt < 2; ++mt)
        #pragma unroll
        for (int nt = 0; nt < 4; ++nt) {
            const __half2 c01 = *reinterpret_cast<const __half2*>(&accc[mt][nt][0]);
            const __half2 c23 = *reinterpret_cast<const __half2*>(&accc[mt][nt][1]);
            acc[mt][nt][0] += __low2float(c01);
            acc[mt][nt][1] += __high2float(c01);
            acc[mt][nt][2] += __low2float(c23);
            acc[mt][nt][3] += __high2float(c23);
        }
}

// ================= pre-pass: split q,k into padded hi/lo planes =================
__global__ void __launch_bounds__(128) k_split_qk(
    const float* __restrict__ q, const float* __restrict__ k)
{
    const int g = blockIdx.x, b = blockIdx.y, br = blockIdx.z;
    const int tid = threadIdx.x;
    const float* src = (br ? k : q) + (size_t)b * (G_ * GS_) + g * GS_;
    const size_t base = ((size_t)(br * G_ + g) * B_ + b) * GSP;
    for (int i = tid; i < GSP; i += 128) {
        const float x = (i < GS_) ? src[i] : 0.0f;
        __half h, l;
        split_f32(x, h, l);
        g_qk_hi[base + i] = h;
        g_qk_lo[base + i] = l;
    }
}

// ================= stage kernels =================

// stage 1: grouped fc1. grid (2, 8, 32)
__global__ void __launch_bounds__(THREADS, 1) k_fc1g(
    const float* __restrict__ Wq1, const float* __restrict__ bq1,
    const float* __restrict__ Wk1, const float* __restrict__ bk1)
{
    const int z = blockIdx.z, br = z >> 4, g = z & 15;
    const int m0 = blockIdx.x * BM, n0 = blockIdx.y * BN;

    const size_t abase = (size_t)(br * G_ + g) * B_ * GSP;
    const float* W    = (br ? Wk1 : Wq1) + (size_t)g * GS_ * HID_;
    const float* bias = (br ? bk1 : bq1) + g * HID_;

    float acc[2][4][4];
    gemm_body<false, false>(g_qk_hi + abase, g_qk_lo + abase, GSP, W, HID_, GS_, m0, n0, acc);

    const int lane = threadIdx.x & 31, wid = threadIdx.x >> 5;
    const int wm = (wid >> 2) * 32, wn = (wid & 3) * 32;
    #pragma unroll
    for (int mt = 0; mt < 2; ++mt) {
        const int r = m0 + wm + mt * 16 + (lane >> 2);
        #pragma unroll
        for (int nt = 0; nt < 4; ++nt) {
            const int c = n0 + wn + nt * 8 + (lane & 3) * 2;
            const float b0 = bias[c], b1 = bias[c + 1];
            const size_t i0 = (size_t)(br * B_ + r) * (G_ * HID_) + (size_t)g * HID_ + c;
            const size_t i1 = i0 + (size_t)8 * (G_ * HID_);
            split_store2(&g_h_hi[i0], &g_h_lo[i0],
                         silu_f(acc[mt][nt][0] + b0), silu_f(acc[mt][nt][1] + b1));
            split_store2(&g_h_hi[i1], &g_h_lo[i1],
                         silu_f(acc[mt][nt][2] + b0), silu_f(acc[mt][nt][3] + b1));
        }
    }
}

// stage 2: grouped fc4, contiguous [row][g][o] store. grid (2, 16, 32)
__global__ void __launch_bounds__(THREADS, 1) k_fc4g(
    const float* __restrict__ Wq4, const float* __restrict__ bq4,
    const float* __restrict__ Wk4, const float* __restrict__ bk4)
{
    const int z = blockIdx.z, br = z >> 4, g = z & 15;
    const int m0 = blockIdx.x * BM, n0 = blockIdx.y * BN;

    const __half* Ah  = g_h_hi + (size_t)br * B_ * G_ * HID_ + (size_t)g * HID_;
    const __half* Al  = g_h_lo + (size_t)br * B_ * G_ * HID_ + (size_t)g * HID_;
    const float* W    = (br ? Wk4 : Wq4) + (size_t)g * HID_ * FEAT_;
    const float* bias = (br ? bk4 : bq4) + g * FEAT_;

    float acc[2][4][4];
    gemm_body<false, true>(Ah, Al, G_ * HID_, W, FEAT_, HID_, m0, n0, acc);

    const int lane = threadIdx.x & 31, wid = threadIdx.x >> 5;
    const int wm = (wid >> 2) * 32, wn = (wid & 3) * 32;
    #pragma unroll
    for (int mt = 0; mt < 2; ++mt) {
        const int r = m0 + wm + mt * 16 + (lane >> 2);
        const size_t rb0 = (size_t)(br * B_ + r)     * (G_ * FEAT_) + (size_t)g * FEAT_;
        const size_t rb1 = (size_t)(br * B_ + r + 8) * (G_ * FEAT_) + (size_t)g * FEAT_;
        #pragma unroll
        for (int nt = 0; nt < 4; ++nt) {
            const int c = n0 + wn + nt * 8 + (lane & 3) * 2;
            const float b0 = bias[c], b1 = bias[c + 1];
            split_store2(&g_f_hi[rb0 + c], &g_f_lo[rb0 + c],
                         silu_f(acc[mt][nt][0] + b0), silu_f(acc[mt][nt][1] + b1));
            split_store2(&g_f_hi[rb1 + c], &g_f_lo[rb1 + c],
                         silu_f(acc[mt][nt][2] + b0), silu_f(acc[mt][nt][3] + b1));
        }
    }
}

// stage 3: global fc1 split-K with permuted weight rows. grid (4, 8, NSPL=32)
__global__ void __launch_bounds__(THREADS, 1) k_gf1(const float* __restrict__ Wg1)
{
    const int s = blockIdx.z;
    const int m0 = blockIdx.x * BM, n0 = blockIdx.y * BN;

    const __half* Ah = g_f_hi + (size_t)s * KSPL;
    const __half* Al = g_f_lo + (size_t)s * KSPL;
    const int koff = (s & 1) * KSPL;
    const int gsel = s >> 1;

    float acc[2][4][4];
    gemm_body<true, true>(Ah, Al, G_ * FEAT_, Wg1, HID_, KSPL, m0, n0, acc, koff, gsel);

    const int lane = threadIdx.x & 31, wid = threadIdx.x >> 5;
    const int wm = (wid >> 2) * 32, wn = (wid & 3) * 32;
    float* P = g_part + (size_t)s * (2 * B_ * HID_);
    #pragma unroll
    for (int mt = 0; mt < 2; ++mt) {
        const int r = m0 + wm + mt * 16 + (lane >> 2);
        #pragma unroll
        for (int nt = 0; nt < 4; ++nt) {
            const int c = n0 + wn + nt * 8 + (lane & 3) * 2;
            P[(size_t)r * HID_ + c]           = acc[mt][nt][0];
            P[(size_t)r * HID_ + c + 1]       = acc[mt][nt][1];
            P[(size_t)(r + 8) * HID_ + c]     = acc[mt][nt][2];
            P[(size_t)(r + 8) * HID_ + c + 1] = acc[mt][nt][3];
        }
    }
}

// reduce NSPL partials + bias + silu -> pre-split g_hg
__global__ void __launch_bounds__(256) k_reduce_silu(const float* __restrict__ bg1)
{
    const int idx = blockIdx.x * blockDim.x + threadIdx.x;
    if (idx >= 2 * B_ * HID_) return;
    const int col = idx & (HID_ - 1);
    float v = bg1[col];
    #pragma unroll
    for (int s = 0; s < NSPL; ++s)
        v += g_part[(size_t)s * (2 * B_ * HID_) + idx];
    v = silu_f(v);
    __half h, l;
    split_f32(v, h, l);
    g_hg_hi[idx] = h;
    g_hg_lo[idx] = l;
}

// stage 4: global fc4 split-K. grid (4, 16, NSPL4=8)
__global__ void __launch_bounds__(THREADS, 1) k_gf4(const float* __restrict__ Wg4)
{
    const int s = blockIdx.z;
    const int m0 = blockIdx.x * BM, n0 = blockIdx.y * BN;

    const __half* Ah = g_hg_hi + (size_t)s * KSPL4;
    const __half* Al = g_hg_lo + (size_t)s * KSPL4;
    const float*  W  = Wg4 + (size_t)s * KSPL4 * FEAT_;

    float acc[2][4][4];
    gemm_body<false, true>(Ah, Al, HID_, W, FEAT_, KSPL4, m0, n0, acc);

    const int lane = threadIdx.x & 31, wid = threadIdx.x >> 5;
    const int wm = (wid >> 2) * 32, wn = (wid & 3) * 32;
    float* P = g_part4 + (size_t)s * (2 * B_ * FEAT_);
    #pragma unroll
    for (int mt = 0; mt < 2; ++mt) {
        const int r = m0 + wm + mt * 16 + (lane >> 2);
        #pragma unroll
        for (int nt = 0; nt < 4; ++nt) {
            const int c = n0 + wn + nt * 8 + (lane & 3) * 2;
            P[(size_t)r * FEAT_ + c]           = acc[mt][nt][0];
            P[(size_t)r * FEAT_ + c + 1]       = acc[mt][nt][1];
            P[(size_t)(r + 8) * FEAT_ + c]     = acc[mt][nt][2];
            P[(size_t)(r + 8) * FEAT_ + c + 1] = acc[mt][nt][3];
        }
    }
}

// fused: reduce NSPL4 partials + bias + silu for q&k rows, dot, store score. grid (B_)
__global__ void __launch_bounds__(256) k_reduce4_dot(const float* __restrict__ bg4)
{
    const int b = blockIdx.x, t = threadIdx.x;
    float s = 0.0f;
    for (int col = t; col < FEAT_; col += 256) {
        float vq = bg4[col];
        float vk = vq;
        #pragma unroll
        for (int sp = 0; sp < NSPL4; ++sp) {
            const float* P = g_part4 + (size_t)sp * (2 * B_ * FEAT_);
            vq += P[(size_t)b * FEAT_ + col];
            vk += P[(size_t)(B_ + b) * FEAT_ + col];
        }
        s = fmaf(silu_f(vq), silu_f(vk), s);
    }
    __shared__ float sh[256];
    sh[t] = s;
    __syncthreads();
    for (int off = 128; off > 0; off >>= 1) {
        if (t < off) sh[t] += sh[t + off];
        __syncthreads();
    }
    if (t == 0) g_scores[b] = sh[0];
}

// softmax over batch
__global__ void __launch_bounds__(256) k_softmax(float* __restrict__ out)
{
    const int t = threadIdx.x;
    __shared__ float sh[256];
    float v = g_scores[t];
    sh[t] = v;
    __syncthreads();
    for (int off = 128; off > 0; off >>= 1) {
        if (t < off) sh[t] = fmaxf(sh[t], sh[t + off]);
        __syncthreads();
    }
    const float m = sh[0];
    __syncthreads();
    const float e = expf(v - m);
    sh[t] = e;
    __syncthreads();
    for (int off = 128; off > 0; off >>= 1) {
        if (t < off) sh[t] += sh[t + off];
        __syncthreads();
    }
    out[t] = e / sh[0];
}

// ================= launch =================
extern "C" void kernel_launch(void* const* d_in, const int* in_sizes, int n_in,
                              void* d_out, int out_size)
{
    const float* q   = (const float*)d_in[0];
    const float* k   = (const float*)d_in[1];
    const float* Wq1 = (const float*)d_in[2];
    const float* bq1 = (const float*)d_in[3];
    const float* Wq4 = (const float*)d_in[4];
    const float* bq4 = (const float*)d_in[5];
    const float* Wk1 = (const float*)d_in[6];
    const float* bk1 = (const float*)d_in[7];
    const float* Wk4 = (const float*)d_in[8];
    const float* bk4 = (const float*)d_in[9];
    const float* Wg1 = (const float*)d_in[10];
    const float* bg1 = (const float*)d_in[11];
    const float* Wg4 = (const float*)d_in[12];
    const float* bg4 = (const float*)d_in[13];
    float* out = (float*)d_out;

    cudaFuncSetAttribute(k_fc1g, cudaFuncAttributeMaxDynamicSharedMemorySize, SMEM_TOTAL);
    cudaFuncSetAttribute(k_fc4g, cudaFuncAttributeMaxDynamicSharedMemorySize, SMEM_TOTAL);
    cudaFuncSetAttribute(k_gf1,  cudaFuncAttributeMaxDynamicSharedMemorySize, SMEM_TOTAL);
    cudaFuncSetAttribute(k_gf4,  cudaFuncAttributeMaxDynamicSharedMemorySize, SMEM_TOTAL);

    k_split_qk<<<dim3(G_, B_, 2), 128>>>(q, k);
    k_fc1g<<<dim3(2, 8, 2 * G_),   THREADS, SMEM_TOTAL>>>(Wq1, bq1, Wk1, bk1);
    k_fc4g<<<dim3(2, 16, 2 * G_),  THREADS, SMEM_TOTAL>>>(Wq4, bq4, Wk4, bk4);
    k_gf1<<<dim3(4, 8, NSPL),      THREADS, SMEM_TOTAL>>>(Wg1);
    k_reduce_silu<<<(2 * B_ * HID_) / 256, 256>>>(bg1);
    k_gf4<<<dim3(4, 16, NSPL4),    THREADS, SMEM_TOTAL>>>(Wg4);
    k_reduce4_dot<<<B_, 256>>>(bg4);
    k_softmax<<<1, 256>>>(out);
}